// round 7
// baseline (speedup 1.0000x reference)
#include <cuda_runtime.h>
#include <cstdint>

#define LOCN  10000
#define DLOC  128
#define DST   64
#define DSUM  256
#define BB    64
#define SS    128
#define NROWS_MAX (BB * SS)    // max unique rows = 8192
#define NBLOCKS   296          // 2 blocks/SM x 148 SMs, all co-resident

// Scratch: Y = relu(A @ W_loc + b)*16 for needed rows (5.12 MB).
__device__ float g_Y[(size_t)LOCN * DLOC];
__device__ int   g_flag[LOCN];     // epoch-tagged marks (never cleared)
__device__ int   g_list[NROWS_MAX];
__device__ int   g_count;          // unique rows this launch
__device__ int   g_work;           // work-stealing cursor
__device__ int   g_epoch;          // bumped at end of each launch
__device__ int   g_bar1, g_bar2, g_bar3;   // grid barriers (reset each launch)

// ---------------------------------------------------------------------------
// Single fused persistent kernel.
//   Phase 1: dedup loc -> g_list (first 8192 threads), epoch-tagged flags.
//   Phase 2: work-stealing SpMM  Y = relu(A@W + b) * 16 over unique rows.
//   Phase 3: grid-stride gather/concat into out.
// Grid-wide sync via atomic arrive + volatile spin; 296 blocks co-resident
// by construction (launch_bounds(256,2) => <=128 regs/thread).
// ---------------------------------------------------------------------------
__global__ void __launch_bounds__(256, 2) fused_kernel(
    const int*   __restrict__ loc,
    const int*   __restrict__ st,
    const int*   __restrict__ ed,
    const float* __restrict__ A,
    const float* __restrict__ W,
    const float* __restrict__ bias,
    const float* __restrict__ emb_st,
    const float* __restrict__ emb_ed,
    float4*      __restrict__ out)
{
    const int tid  = blockIdx.x * 256 + threadIdx.x;
    const int lane = threadIdx.x & 31;
    const int e    = g_epoch + 1;              // this launch's epoch

    // ---------------- Phase 1: mark + compact (threads 0..8191) ----------
    if (tid < BB * SS) {
        const int r   = loc[tid];
        const int old = atomicExch(&g_flag[r], e);
        const bool first = (old != e);
        const unsigned mask = __ballot_sync(0xffffffffu, first);
        int base = 0;
        if (lane == 0 && mask) base = atomicAdd(&g_count, __popc(mask));
        base = __shfl_sync(0xffffffffu, base, 0);
        if (first) {
            const int pos = base + __popc(mask & ((1u << lane) - 1u));
            g_list[pos] = r;
        }
    }
    __threadfence();

    // ---------------- Barrier 1 ------------------------------------------
    __syncthreads();
    if (threadIdx.x == 0) {
        atomicAdd(&g_bar1, 1);
        while (*(volatile int*)&g_bar1 < NBLOCKS) { }
    }
    __syncthreads();
    __threadfence();

    // ---------------- Phase 2: work-stealing SpMM ------------------------
    {
        const int count = *(volatile int*)&g_count;

        constexpr int NV4   = LOCN / 4;                // 2500
        constexpr int K     = 8;                       // float4/lane/iter
        constexpr int VPI   = 32 * K;                  // 256 float4/warp/iter
        constexpr int NITER = (NV4 + VPI - 1) / VPI;   // 10
        const float4 Z = make_float4(0.f, 0.f, 0.f, 0.f);

        const float b0v = bias[lane];
        const float b1v = bias[lane + 32];
        const float b2v = bias[lane + 64];
        const float b3v = bias[lane + 96];

        for (;;) {
            int widx = 0;
            if (lane == 0) widx = atomicAdd(&g_work, 1);
            widx = __shfl_sync(0xffffffffu, widx, 0);
            if (widx >= count) break;
            const int row_idx = g_list[widx];

            const float4* __restrict__ row =
                reinterpret_cast<const float4*>(A + (size_t)row_idx * LOCN);

            float acc0 = 0.f, acc1 = 0.f, acc2 = 0.f, acc3 = 0.f;

            float4 cur[K], nxt[K];
            #pragma unroll
            for (int k = 0; k < K; ++k) {
                const int idx = lane + 32 * k;
                cur[k] = (idx < NV4) ? __ldcs(&row[idx]) : Z;
            }

            for (int it = 0; it < NITER; ++it) {
                if (it + 1 < NITER) {
                    const int nbase = (it + 1) * VPI + lane;
                    #pragma unroll
                    for (int k = 0; k < K; ++k) {
                        const int idx = nbase + 32 * k;
                        nxt[k] = (idx < NV4) ? __ldcs(&row[idx]) : Z;
                    }
                }

                #pragma unroll
                for (int k = 0; k < K; ++k) {
                    const float4 v = cur[k];
                    const bool nz = (v.x != 0.f) | (v.y != 0.f) |
                                    (v.z != 0.f) | (v.w != 0.f);
                    unsigned m = __ballot_sync(0xffffffffu, nz);
                    while (m) {
                        const int j = __ffs(m) - 1;
                        m &= m - 1;
                        const float vx = __shfl_sync(0xffffffffu, v.x, j);
                        const float vy = __shfl_sync(0xffffffffu, v.y, j);
                        const float vz = __shfl_sync(0xffffffffu, v.z, j);
                        const float vw = __shfl_sync(0xffffffffu, v.w, j);
                        const int n0 = (it * VPI + k * 32 + j) * 4;

                        const float* __restrict__ Wr =
                            W + (size_t)n0 * DLOC + lane;
                        if (vx != 0.f) {
                            acc0 = fmaf(vx, Wr[0],  acc0);
                            acc1 = fmaf(vx, Wr[32], acc1);
                            acc2 = fmaf(vx, Wr[64], acc2);
                            acc3 = fmaf(vx, Wr[96], acc3);
                        }
                        Wr += DLOC;
                        if (vy != 0.f) {
                            acc0 = fmaf(vy, Wr[0],  acc0);
                            acc1 = fmaf(vy, Wr[32], acc1);
                            acc2 = fmaf(vy, Wr[64], acc2);
                            acc3 = fmaf(vy, Wr[96], acc3);
                        }
                        Wr += DLOC;
                        if (vz != 0.f) {
                            acc0 = fmaf(vz, Wr[0],  acc0);
                            acc1 = fmaf(vz, Wr[32], acc1);
                            acc2 = fmaf(vz, Wr[64], acc2);
                            acc3 = fmaf(vz, Wr[96], acc3);
                        }
                        Wr += DLOC;
                        if (vw != 0.f) {
                            acc0 = fmaf(vw, Wr[0],  acc0);
                            acc1 = fmaf(vw, Wr[32], acc1);
                            acc2 = fmaf(vw, Wr[64], acc2);
                            acc3 = fmaf(vw, Wr[96], acc3);
                        }
                    }
                }

                #pragma unroll
                for (int k = 0; k < K; ++k) cur[k] = nxt[k];
            }

            const float s = 16.0f;
            float* __restrict__ y = g_Y + (size_t)row_idx * DLOC + lane;
            y[0]  = fmaxf(acc0 + b0v, 0.f) * s;
            y[32] = fmaxf(acc1 + b1v, 0.f) * s;
            y[64] = fmaxf(acc2 + b2v, 0.f) * s;
            y[96] = fmaxf(acc3 + b3v, 0.f) * s;
        }
    }
    __threadfence();

    // ---------------- Barrier 2 ------------------------------------------
    __syncthreads();
    if (threadIdx.x == 0) {
        atomicAdd(&g_bar2, 1);
        while (*(volatile int*)&g_bar2 < NBLOCKS) { }
    }
    __syncthreads();
    __threadfence();

    // ---------------- Phase 3: gather/concat (grid-stride) ---------------
    {
        constexpr int N1V = BB * SS * DSUM / 4;         // 524288
        constexpr int NTV = N1V + BB * SS * DST / 4;    // 655360
        constexpr int NTHREADS = NBLOCKS * 256;         // 75776

        const float4* __restrict__ Yv  = reinterpret_cast<const float4*>(g_Y);
        const float4* __restrict__ stv = reinterpret_cast<const float4*>(emb_st);
        const float4* __restrict__ edv = reinterpret_cast<const float4*>(emb_ed);
        const float s = 16.0f;

        for (int idx = tid; idx < NTV; idx += NTHREADS) {
            float4 r;
            if (idx < N1V) {
                const int bs = idx >> 6;
                const int d4 = idx & 63;
                if (d4 < 32) {                            // loc (pre-scaled)
                    r = Yv[(size_t)loc[bs] * 32 + d4];
                } else if (d4 < 48) {                     // st
                    r = stv[st[bs] * 16 + (d4 - 32)];
                    r.x *= s; r.y *= s; r.z *= s; r.w *= s;
                } else {                                  // ed
                    r = edv[ed[bs] * 16 + (d4 - 48)];
                    r.x *= s; r.y *= s; r.z *= s; r.w *= s;
                }
            } else {
                const int j  = idx - N1V;
                const int bs = j >> 4;
                const int d4 = j & 15;
                const int ss = bs & (SS - 1);
                const int yt = (ss < SS - 1) ? st[bs + 1] : 0;
                r = stv[yt * 16 + d4];                    // res_yt NOT scaled
            }
            out[idx] = r;
        }
    }

    // ---------------- Exit: last block resets bookkeeping -----------------
    __syncthreads();
    if (threadIdx.x == 0) {
        __threadfence();
        const int prev = atomicAdd(&g_bar3, 1);
        if (prev == NBLOCKS - 1) {
            g_bar1 = 0;
            g_bar2 = 0;
            g_bar3 = 0;
            g_count = 0;
            g_work  = 0;
            g_epoch = e;        // next launch uses e+1
            __threadfence();
        }
    }
}

extern "C" void kernel_launch(void* const* d_in, const int* in_sizes, int n_in,
                              void* d_out, int out_size)
{
    const int*   loc    = (const int*)  d_in[0];
    const int*   st     = (const int*)  d_in[1];
    const int*   ed     = (const int*)  d_in[2];
    const float* A      = (const float*)d_in[3];
    const float* W_loc  = (const float*)d_in[4];
    const float* b_loc  = (const float*)d_in[5];
    const float* emb_st = (const float*)d_in[6];
    const float* emb_ed = (const float*)d_in[7];

    fused_kernel<<<NBLOCKS, 256>>>(
        loc, st, ed, A, W_loc, b_loc, emb_st, emb_ed, (float4*)d_out);
}

// round 8
// speedup vs baseline: 1.1155x; 1.1155x over previous
#include <cuda_runtime.h>
#include <cstdint>

#define LOCN  10000
#define DLOC  128
#define DST   64
#define DSUM  256
#define BB    64
#define SS    128
#define NIDX  (BB * SS)        // 8192 loc entries (with duplicates)

// Scratch: Y = relu(A @ W_loc + b)*16 for needed rows (5.12 MB).
__device__ float g_Y[(size_t)LOCN * DLOC];
__device__ int   g_flag[LOCN];     // epoch-tagged claims (never cleared)
__device__ int   g_work;           // work-stealing cursor over loc entries
__device__ int   g_epoch;          // bumped by gather kernel each launch

// ---------------------------------------------------------------------------
// Kernel 1: SpMM with INLINE dedup. Persistent warps steal indices over the
// 8192 loc entries; first warp to claim a row (epoch atomicExch) computes
// Y[row] = relu(A[row] @ W + b) * 16. Duplicate pops cost ~600 cyc and are
// negligible vs ~7 us of row work. No separate mark kernel, no barrier.
// Per row: 8 float4/lane/iter with next-iter prefetch (16 loads in flight).
// ---------------------------------------------------------------------------
__global__ void __launch_bounds__(256, 2) spmm_dedup_kernel(
    const int*   __restrict__ loc,
    const float* __restrict__ A,
    const float* __restrict__ W,
    const float* __restrict__ bias)
{
    const int lane = threadIdx.x & 31;
    const int e    = g_epoch + 1;                      // this launch's epoch

    constexpr int NV4   = LOCN / 4;                    // 2500
    constexpr int K     = 8;                           // float4/lane/iter
    constexpr int VPI   = 32 * K;                      // 256 float4/warp/iter
    constexpr int NITER = (NV4 + VPI - 1) / VPI;       // 10
    const float4 Z = make_float4(0.f, 0.f, 0.f, 0.f);

    const float b0v = bias[lane];
    const float b1v = bias[lane + 32];
    const float b2v = bias[lane + 64];
    const float b3v = bias[lane + 96];

    for (;;) {
        // Pop a loc entry; claim its row via epoch exchange (lane 0).
        int widx = 0, claimed = 0, row_idx = 0;
        if (lane == 0) {
            widx = atomicAdd(&g_work, 1);
            if (widx < NIDX) {
                row_idx = __ldg(&loc[widx]);
                claimed = (atomicExch(&g_flag[row_idx], e) != e);
            }
        }
        widx    = __shfl_sync(0xffffffffu, widx, 0);
        if (widx >= NIDX) return;
        claimed = __shfl_sync(0xffffffffu, claimed, 0);
        if (!claimed) continue;                        // duplicate row
        row_idx = __shfl_sync(0xffffffffu, row_idx, 0);

        const float4* __restrict__ row =
            reinterpret_cast<const float4*>(A + (size_t)row_idx * LOCN);

        float acc0 = 0.f, acc1 = 0.f, acc2 = 0.f, acc3 = 0.f;

        float4 cur[K], nxt[K];
        #pragma unroll
        for (int k = 0; k < K; ++k) {
            const int idx = lane + 32 * k;
            cur[k] = (idx < NV4) ? __ldcs(&row[idx]) : Z;
        }

        for (int it = 0; it < NITER; ++it) {
            if (it + 1 < NITER) {
                const int nbase = (it + 1) * VPI + lane;
                #pragma unroll
                for (int k = 0; k < K; ++k) {
                    const int idx = nbase + 32 * k;
                    nxt[k] = (idx < NV4) ? __ldcs(&row[idx]) : Z;
                }
            }

            #pragma unroll
            for (int k = 0; k < K; ++k) {
                const float4 v = cur[k];
                const bool nz = (v.x != 0.f) | (v.y != 0.f) |
                                (v.z != 0.f) | (v.w != 0.f);
                unsigned m = __ballot_sync(0xffffffffu, nz);
                while (m) {
                    const int j = __ffs(m) - 1;
                    m &= m - 1;
                    const float vx = __shfl_sync(0xffffffffu, v.x, j);
                    const float vy = __shfl_sync(0xffffffffu, v.y, j);
                    const float vz = __shfl_sync(0xffffffffu, v.z, j);
                    const float vw = __shfl_sync(0xffffffffu, v.w, j);
                    const int n0 = (it * VPI + k * 32 + j) * 4;

                    const float* __restrict__ Wr = W + (size_t)n0 * DLOC + lane;
                    if (vx != 0.f) {
                        acc0 = fmaf(vx, Wr[0],  acc0);
                        acc1 = fmaf(vx, Wr[32], acc1);
                        acc2 = fmaf(vx, Wr[64], acc2);
                        acc3 = fmaf(vx, Wr[96], acc3);
                    }
                    Wr += DLOC;
                    if (vy != 0.f) {
                        acc0 = fmaf(vy, Wr[0],  acc0);
                        acc1 = fmaf(vy, Wr[32], acc1);
                        acc2 = fmaf(vy, Wr[64], acc2);
                        acc3 = fmaf(vy, Wr[96], acc3);
                    }
                    Wr += DLOC;
                    if (vz != 0.f) {
                        acc0 = fmaf(vz, Wr[0],  acc0);
                        acc1 = fmaf(vz, Wr[32], acc1);
                        acc2 = fmaf(vz, Wr[64], acc2);
                        acc3 = fmaf(vz, Wr[96], acc3);
                    }
                    Wr += DLOC;
                    if (vw != 0.f) {
                        acc0 = fmaf(vw, Wr[0],  acc0);
                        acc1 = fmaf(vw, Wr[32], acc1);
                        acc2 = fmaf(vw, Wr[64], acc2);
                        acc3 = fmaf(vw, Wr[96], acc3);
                    }
                }
            }

            #pragma unroll
            for (int k = 0; k < K; ++k) cur[k] = nxt[k];
        }

        const float s = 16.0f;
        float* __restrict__ y = g_Y + (size_t)row_idx * DLOC + lane;
        y[0]  = fmaxf(acc0 + b0v, 0.f) * s;
        y[32] = fmaxf(acc1 + b1v, 0.f) * s;
        y[64] = fmaxf(acc2 + b2v, 0.f) * s;
        y[96] = fmaxf(acc3 + b3v, 0.f) * s;
    }
}

// ---------------------------------------------------------------------------
// Kernel 2: assemble outputs (float4), 4 independent elements per thread.
// Also bumps epoch / resets the cursor for the next launch (graph-ordered
// before the next launch's spmm).
// ---------------------------------------------------------------------------
__global__ void __launch_bounds__(256) gather_concat_kernel(
    const int*   __restrict__ loc,
    const int*   __restrict__ st,
    const int*   __restrict__ ed,
    const float* __restrict__ emb_st,
    const float* __restrict__ emb_ed,
    float4*      __restrict__ out)
{
    constexpr int N1V  = BB * SS * DSUM / 4;           // 524288
    constexpr int NTV  = N1V + BB * SS * DST / 4;      // 655360
    constexpr int QTR  = NTV / 4;                      // 163840

    const int tid = blockIdx.x * blockDim.x + threadIdx.x;
    if (tid >= QTR) return;

    if (tid == 0) {
        g_epoch = g_epoch + 1;
        g_work  = 0;
    }

    const float4* __restrict__ Yv  = reinterpret_cast<const float4*>(g_Y);
    const float4* __restrict__ stv = reinterpret_cast<const float4*>(emb_st);
    const float4* __restrict__ edv = reinterpret_cast<const float4*>(emb_ed);
    const float s = 16.0f;

    #pragma unroll
    for (int h = 0; h < 4; ++h) {
        const int idx = tid + h * QTR;
        float4 r;
        if (idx < N1V) {
            const int bs = idx >> 6;
            const int d4 = idx & 63;
            if (d4 < 32) {                               // loc (pre-scaled)
                r = Yv[(size_t)loc[bs] * 32 + d4];
            } else if (d4 < 48) {                        // st
                r = stv[st[bs] * 16 + (d4 - 32)];
                r.x *= s; r.y *= s; r.z *= s; r.w *= s;
            } else {                                     // ed
                r = edv[ed[bs] * 16 + (d4 - 48)];
                r.x *= s; r.y *= s; r.z *= s; r.w *= s;
            }
        } else {
            const int j  = idx - N1V;
            const int bs = j >> 4;
            const int d4 = j & 15;
            const int ss = bs & (SS - 1);
            const int yt = (ss < SS - 1) ? st[bs + 1] : 0;
            r = stv[yt * 16 + d4];                       // res_yt NOT scaled
        }
        out[idx] = r;
    }
}

extern "C" void kernel_launch(void* const* d_in, const int* in_sizes, int n_in,
                              void* d_out, int out_size)
{
    const int*   loc    = (const int*)  d_in[0];
    const int*   st     = (const int*)  d_in[1];
    const int*   ed     = (const int*)  d_in[2];
    const float* A      = (const float*)d_in[3];
    const float* W_loc  = (const float*)d_in[4];
    const float* b_loc  = (const float*)d_in[5];
    const float* emb_st = (const float*)d_in[6];
    const float* emb_ed = (const float*)d_in[7];

    // Kernel 1: persistent work-stealing SpMM with inline dedup.
    spmm_dedup_kernel<<<296, 256>>>(loc, A, W_loc, b_loc);

    // Kernel 2: gather + concat + bookkeeping reset.
    constexpr int qtr = (BB * SS * DSUM + BB * SS * DST) / 4 / 4;
    gather_concat_kernel<<<(qtr + 255) / 256, 256>>>(
        loc, st, ed, emb_st, emb_ed, (float4*)d_out);
}